// round 9
// baseline (speedup 1.0000x reference)
#include <cuda_runtime.h>
#include <cuda_bf16.h>

// F0 via raw autocorrelation argmax (per-frame normalization is a positive
// scalar -> argmax invariant -> skipped).
// R2: frame-pairs packed in f32x2; all inner math fma.rn.f32x2.
// R7: ping-pong window banks A/B, 16-step unrolled chunks, chunk prefetch.
// R8: occupancy 4 -> 5 blocks/SM. Smem cut 47.3KB -> 32KB by dropping the
//     zero tail (BUF=512); triangle masking via predicated prefetch
//     (ISETP + @p LDS, preset 0) on the latency-tolerant prefetch path.
//     __launch_bounds__(256,5) caps regs at ~51 (live set ~50 fits).

#define SR_I        16000
#define HOP         256
#define FRAME_LEN   512
#define MIN_PERIOD  32
#define LAGS_PER_LANE 7
#define PAIRS_PER_BLOCK 8      // 8 warps, each warp = 2 frames
#define T_LEN       163840
#define N_FRAMES    641
#define BUF         512        // data only; OOB window values come from predication

#define FMA_F32X2(d, a, b, c) \
    asm("fma.rn.f32x2 %0, %1, %2, %3;" : "=l"(d) : "l"(a), "l"(b), "l"(c))

__device__ __forceinline__ unsigned long long pack2(float2 v) {
    unsigned long long r;
    asm("mov.b64 %0, {%1, %2};" : "=l"(r) : "f"(v.x), "f"(v.y));
    return r;
}
__device__ __forceinline__ float2 unpack2(unsigned long long v) {
    float2 r;
    asm("mov.b64 {%0, %1}, %2;" : "=f"(r.x), "=f"(r.y) : "l"(v));
    return r;
}

__global__ __launch_bounds__(256, 5) void f0_autocorr_r8_kernel(
    const float* __restrict__ x,   // (64, 1, 163840)
    float* __restrict__ out)       // (64, 641)
{
    __shared__ float2 sbuf[PAIRS_PER_BLOCK][BUF];   // 32 KB

    const int b      = blockIdx.y;
    const int f_base = blockIdx.x * (2 * PAIRS_PER_BLOCK);
    const float* __restrict__ xb = x + (size_t)b * T_LEN;
    const int tid = threadIdx.x;

    // Fill: pair p holds frames (f_base+2p, f_base+2p+1) interleaved.
    // xpad[j] = x[reflect(j-256)] (numpy 'reflect', pad = 256).
    for (int i = tid; i < PAIRS_PER_BLOCK * BUF; i += 256) {
        const int p = i >> 9;          // /512
        const int j = i & 511;
        const int fr = f_base + 2 * p;
        int g0 = fr * HOP + j - (FRAME_LEN / 2);
        int g1 = g0 + HOP;
        if (g0 < 0) g0 = -g0;
        if (g0 >= T_LEN) g0 = 2 * (T_LEN - 1) - g0;
        if (g1 >= T_LEN) g1 = 2 * (T_LEN - 1) - g1;
        sbuf[p][j] = make_float2(xb[g0], xb[g1]);
    }
    __syncthreads();

    const int w    = tid >> 5;
    const int lane = tid & 31;
    const float2* __restrict__ s2 = sbuf[w];

    const int base = MIN_PERIOD + LAGS_PER_LANE * lane;   // 32..249

    unsigned long long acc[LAGS_PER_LANE];
#pragma unroll
    for (int k = 0; k < LAGS_PER_LANE; ++k) acc[k] = 0ull;

    // Predicated window fetch: values at frame index >= 512 are zero.
    // On the prefetch path only -> compare/select latency is hidden.
#define WFETCH(dst, jf_) do {                                   \
        const int _jf = (jf_);                                  \
        unsigned long long _v = 0ull;                           \
        if (_jf < FRAME_LEN) _v = pack2(s2[_jf]);               \
        (dst) = _v;                                             \
    } while (0)

    unsigned long long A[8], B[8];
#pragma unroll
    for (int k = 0; k < 8; ++k) A[k] = pack2(s2[base + k]);   // base+7 <= 256: in-range

    int t = 0;
#pragma unroll 1
    for (int c = 0; c < 30; ++c) {          // 30 * 16 = 480 steps
        // ---- half-chunk 1: window in A, prefetch B ----
#pragma unroll
        for (int k = 0; k < 8; ++k) WFETCH(B[k], t + base + 8 + k);
#pragma unroll
        for (int j = 0; j < 8; ++j) {
            const unsigned long long sb = pack2(s2[t + j]);  // broadcast, in-range
#pragma unroll
            for (int k = 0; k < LAGS_PER_LANE; ++k) {
                const int idx = j + k;                       // 0..13
                FMA_F32X2(acc[k], sb, (idx < 8) ? A[idx] : B[idx - 8], acc[k]);
            }
        }
        t += 8;
        // ---- half-chunk 2: window in B, prefetch A ----
#pragma unroll
        for (int k = 0; k < 8; ++k) WFETCH(A[k], t + base + 8 + k);
#pragma unroll
        for (int j = 0; j < 8; ++j) {
            const unsigned long long sb = pack2(s2[t + j]);
#pragma unroll
            for (int k = 0; k < LAGS_PER_LANE; ++k) {
                const int idx = j + k;
                FMA_F32X2(acc[k], sb, (idx < 8) ? B[idx] : A[idx - 8], acc[k]);
            }
        }
        t += 8;
    }
#undef WFETCH

    // Per-lane argmax per packed frame (lowest lag wins ties).
    float bvx, bvy; int bpx, bpy;
    {
        float2 a0 = unpack2(acc[0]);
        bvx = a0.x; bvy = a0.y; bpx = base; bpy = base;
#pragma unroll
        for (int k = 1; k < LAGS_PER_LANE; ++k) {
            float2 a = unpack2(acc[k]);
            if (a.x > bvx) { bvx = a.x; bpx = base + k; }
            if (a.y > bvy) { bvy = a.y; bpy = base + k; }
        }
    }

    // Warp argmax, lowest-lag tie break.
#pragma unroll
    for (int off = 16; off > 0; off >>= 1) {
        const float ovx = __shfl_xor_sync(0xffffffffu, bvx, off);
        const int   opx = __shfl_xor_sync(0xffffffffu, bpx, off);
        const float ovy = __shfl_xor_sync(0xffffffffu, bvy, off);
        const int   opy = __shfl_xor_sync(0xffffffffu, bpy, off);
        if (ovx > bvx || (ovx == bvx && opx < bpx)) { bvx = ovx; bpx = opx; }
        if (ovy > bvy || (ovy == bvy && opy < bpy)) { bvy = ovy; bpy = opy; }
    }

    if (lane == 0) {
        const int fr = f_base + 2 * w;
        if (fr < N_FRAMES) {
            float r = (float)SR_I / ((float)bpx + 1e-8f);
            out[(size_t)b * N_FRAMES + fr] = fminf(fmaxf(r, 50.0f), 500.0f);
        }
        if (fr + 1 < N_FRAMES) {
            float r = (float)SR_I / ((float)bpy + 1e-8f);
            out[(size_t)b * N_FRAMES + fr + 1] = fminf(fmaxf(r, 50.0f), 500.0f);
        }
    }
}

extern "C" void kernel_launch(void* const* d_in, const int* in_sizes, int n_in,
                              void* d_out, int out_size)
{
    const float* x = (const float*)d_in[0];
    float* out = (float*)d_out;
    const int pairs = (N_FRAMES + 1) / 2;                       // 321
    dim3 grid((pairs + PAIRS_PER_BLOCK - 1) / PAIRS_PER_BLOCK,  // 41
              64);
    f0_autocorr_r8_kernel<<<grid, 256>>>(x, out);
}